// round 16
// baseline (speedup 1.0000x reference)
#include <cuda_runtime.h>
#include <cuda_bf16.h>
#include <math_constants.h>
#include <cstdint>
#include <cstddef>

#define BSZ    4
#define SEQ    4096
#define DMODEL 1024
#define HD     64
#define NQ     (BSZ * SEQ)

#define TQ     64           // queries per CTA (2 CTAs/SM) in attention
#define TK     128
#define NTILES (SEQ / TK)   // 32

// Projected q (= k = v) as fp16, PRE-SWIZZLED in 16KB blocks of 128 rows.
__device__ __align__(16) uint32_t g_Qf[(size_t)NQ * HD / 2];
// Split-K fp32 partials: [ks][row*64+col]
__device__ __align__(16) float g_part[4][(size_t)NQ * HD];

// ---------------------------------------------------------------------------
// helpers
// ---------------------------------------------------------------------------
__device__ __forceinline__ uint32_t smem_u32(const void* p) {
    uint32_t a;
    asm("{ .reg .u64 t; cvta.to.shared.u64 t, %1; cvt.u32.u64 %0, t; }"
        : "=r"(a) : "l"(p));
    return a;
}
__device__ __forceinline__ float ex2f(float x) {
    float y; asm("ex2.approx.ftz.f32 %0, %1;" : "=f"(y) : "f"(x)); return y;
}
__device__ __forceinline__ uint32_t packbf(float lo, float hi) {
    uint32_t r;
    asm("cvt.rn.bf16x2.f32 %0, %1, %2;" : "=r"(r) : "f"(hi), "f"(lo));
    return r;
}
__device__ __forceinline__ uint32_t packh(float lo, float hi) {
    uint32_t r;
    asm("cvt.rn.f16x2.f32 %0, %1, %2;" : "=r"(r) : "f"(hi), "f"(lo));
    return r;
}

#define SWZ(o) ((o) ^ (((o) >> 3) & 0x70))

__device__ __forceinline__ void ldsm_x4(uint32_t r[4], uint32_t addr) {
    asm volatile("ldmatrix.sync.aligned.m8n8.x4.shared.b16 {%0,%1,%2,%3}, [%4];"
                 : "=r"(r[0]), "=r"(r[1]), "=r"(r[2]), "=r"(r[3]) : "r"(addr));
}
__device__ __forceinline__ void ldsm_x4t(uint32_t r[4], uint32_t addr) {
    asm volatile("ldmatrix.sync.aligned.m8n8.x4.trans.shared.b16 {%0,%1,%2,%3}, [%4];"
                 : "=r"(r[0]), "=r"(r[1]), "=r"(r[2]), "=r"(r[3]) : "r"(addr));
}
// bf16 mma (projection)
__device__ __forceinline__ void mma16816(float d[4], const uint32_t a[4],
                                         const uint32_t b[2]) {
    asm volatile(
        "mma.sync.aligned.m16n8k16.row.col.f32.bf16.bf16.f32 "
        "{%0,%1,%2,%3}, {%4,%5,%6,%7}, {%8,%9}, {%0,%1,%2,%3};"
        : "+f"(d[0]), "+f"(d[1]), "+f"(d[2]), "+f"(d[3])
        : "r"(a[0]), "r"(a[1]), "r"(a[2]), "r"(a[3]), "r"(b[0]), "r"(b[1]));
}
// fp16 mma (attention)
__device__ __forceinline__ void mma16816h(float d[4], const uint32_t a[4],
                                          const uint32_t b[2]) {
    asm volatile(
        "mma.sync.aligned.m16n8k16.row.col.f32.f16.f16.f32 "
        "{%0,%1,%2,%3}, {%4,%5,%6,%7}, {%8,%9}, {%0,%1,%2,%3};"
        : "+f"(d[0]), "+f"(d[1]), "+f"(d[2]), "+f"(d[3])
        : "r"(a[0]), "r"(a[1]), "r"(a[2]), "r"(a[3]), "r"(b[0]), "r"(b[1]));
}

#define CP16(dst, src) \
    asm volatile("cp.async.cg.shared.global [%0], [%1], 16;" :: "r"(dst), "l"(src))
#define CP_COMMIT() asm volatile("cp.async.commit_group;" ::: "memory")
#define CP_WAIT(n)  asm volatile("cp.async.wait_group %0;" :: "n"(n) : "memory")

__device__ __forceinline__ void split_store4(char* base_h, char* base_l, uint32_t off,
                                             float v0, float v1, float v2, float v3) {
    uint32_t h0 = packbf(v0, v1);
    uint32_t h1 = packbf(v2, v3);
    float f00 = __uint_as_float(h0 << 16);
    float f01 = __uint_as_float(h0 & 0xffff0000u);
    float f10 = __uint_as_float(h1 << 16);
    float f11 = __uint_as_float(h1 & 0xffff0000u);
    uint32_t l0 = packbf(v0 - f00, v1 - f01);
    uint32_t l1 = packbf(v2 - f10, v3 - f11);
    *(uint2*)(base_h + off) = make_uint2(h0, h1);
    *(uint2*)(base_l + off) = make_uint2(l0, l1);
}

// ---------------------------------------------------------------------------
// Kernel 1: Q projection, bf16x3 tensor GEMM, SPLIT-K=4.
// grid (128 row-blocks, 4 k-splits), 128 threads, 3 CTAs/SM.
// Each CTA: 4 serial chunks of K=64; fp32 partials to g_part[ks].
// ---------------------------------------------------------------------------
#define PX_H 0
#define PX_L 16384
#define PW_H 32768
#define PW_L 40960

__global__ __launch_bounds__(128, 3) void qproj_kernel(const float* __restrict__ X,
                                                       const float* __restrict__ W) {
    __shared__ __align__(1024) char psm[49152];
    const uint32_t sb = smem_u32(psm);

    const int tid  = threadIdx.x;
    const int wid  = tid >> 5;          // 0..3
    const int lane = tid & 31;
    const int quad = lane >> 2;
    const int tq   = lane & 3;
    const int row0 = blockIdx.x * 128;
    const int ks   = blockIdx.y;        // 0..3

    const uint32_t xorv  = (uint32_t)(lane & 7) << 4;
    const uint32_t browb = (uint32_t)(((lane >> 4) * 8) + (lane & 7)) * 128;
    const uint32_t qrow_l = (uint32_t)((lane & 7) + ((lane >> 3) & 1) * 8);
    uint32_t qc[4], bc[4];
    #pragma unroll
    for (int c = 0; c < 4; ++c) {
        qc[c] = ((uint32_t)((lane >> 4) * 16 + c * 32)) ^ xorv;
        bc[c] = ((uint32_t)(((lane >> 3) & 1) * 16 + c * 32)) ^ xorv;
    }

    float accQ[2][8][4] = {};

    #pragma unroll 1
    for (int kci = 0; kci < 4; ++kci) {
        const int kc = ks * 4 + kci;
        // convert X chunk [128][64] -> split bf16 (16 float4/thread)
        #pragma unroll
        for (int it = 0; it < 16; ++it) {
            int idx = tid + it * 128;           // 0..2047
            int r = idx >> 4, c4 = idx & 15;
            float4 v = *(const float4*)(X + (size_t)(row0 + r) * DMODEL + kc * 64 + c4 * 4);
            split_store4(psm + PX_H, psm + PX_L, SWZ((uint32_t)(r * 128 + c4 * 8)),
                         v.x, v.y, v.z, v.w);
        }
        // convert W chunk [64][64] (8 float4/thread)
        #pragma unroll
        for (int it = 0; it < 8; ++it) {
            int idx = tid + it * 128;           // 0..1023
            int n = idx >> 4, c4 = idx & 15;
            float4 v = *(const float4*)(W + (size_t)n * DMODEL + kc * 64 + c4 * 4);
            split_store4(psm + PW_H, psm + PW_L, SWZ((uint32_t)(n * 128 + c4 * 8)),
                         v.x, v.y, v.z, v.w);
        }
        __syncthreads();

        // MMA: warp covers 32 rows (2 m16 tiles)
        #pragma unroll
        for (int mt = 0; mt < 2; ++mt) {
            const uint32_t qrowb = ((uint32_t)(wid * 32 + mt * 16) + qrow_l) * 128;
            uint32_t ah[4][4], al[4][4];
            #pragma unroll
            for (int c = 0; c < 4; ++c) {
                ldsm_x4(ah[c], sb + PX_H + qrowb + qc[c]);
                ldsm_x4(al[c], sb + PX_L + qrowb + qc[c]);
            }
            #pragma unroll
            for (int njp = 0; njp < 4; ++njp) {
                #pragma unroll
                for (int c = 0; c < 4; ++c) {
                    uint32_t bh[4], bl[4];
                    ldsm_x4(bh, sb + PW_H + browb + bc[c] + (uint32_t)(njp * 2048));
                    ldsm_x4(bl, sb + PW_L + browb + bc[c] + (uint32_t)(njp * 2048));
                    mma16816(accQ[mt][njp * 2],     ah[c], bh);
                    mma16816(accQ[mt][njp * 2 + 1], ah[c], bh + 2);
                    mma16816(accQ[mt][njp * 2],     ah[c], bl);
                    mma16816(accQ[mt][njp * 2 + 1], ah[c], bl + 2);
                    mma16816(accQ[mt][njp * 2],     al[c], bh);
                    mma16816(accQ[mt][njp * 2 + 1], al[c], bh + 2);
                }
            }
        }
        __syncthreads();
    }

    // epilogue: fp32 partials to g_part[ks]
    float* gp = g_part[ks];
    #pragma unroll
    for (int mt = 0; mt < 2; ++mt) {
        #pragma unroll
        for (int nj = 0; nj < 8; ++nj) {
            const int rA  = row0 + wid * 32 + mt * 16 + quad;
            const int col = nj * 8 + tq * 2;
            *(float2*)(gp + (size_t)rA * 64 + col) =
                make_float2(accQ[mt][nj][0], accQ[mt][nj][1]);
            *(float2*)(gp + (size_t)(rA + 8) * 64 + col) =
                make_float2(accQ[mt][nj][2], accQ[mt][nj][3]);
        }
    }
}

// ---------------------------------------------------------------------------
// Kernel 1b: finalize — sum 4 partials, pack fp16, swizzled store to g_Qf.
// 128 CTAs x 256 threads; 4 x 16B output units per thread.
// ---------------------------------------------------------------------------
__global__ __launch_bounds__(256, 1) void qfin_kernel() {
    const int t = blockIdx.x * 256 + threadIdx.x;     // 0..32767
    const float4* p0 = (const float4*)g_part[0];
    const float4* p1 = (const float4*)g_part[1];
    const float4* p2 = (const float4*)g_part[2];
    const float4* p3 = (const float4*)g_part[3];
    #pragma unroll
    for (int i = 0; i < 4; ++i) {
        const int u = t + i * 32768;                  // 0..131071 (16B units)
        const int row  = u >> 3;
        const int colu = u & 7;
        const size_t fb = (size_t)u * 2;
        float4 a0 = p0[fb],     a1 = p1[fb],     a2 = p2[fb],     a3 = p3[fb];
        float4 b0 = p0[fb + 1], b1 = p1[fb + 1], b2 = p2[fb + 1], b3 = p3[fb + 1];
        float4 a = make_float4(a0.x + a1.x + a2.x + a3.x,
                               a0.y + a1.y + a2.y + a3.y,
                               a0.z + a1.z + a2.z + a3.z,
                               a0.w + a1.w + a2.w + a3.w);
        float4 b = make_float4(b0.x + b1.x + b2.x + b3.x,
                               b0.y + b1.y + b2.y + b3.y,
                               b0.z + b1.z + b2.z + b3.z,
                               b0.w + b1.w + b2.w + b3.w);
        uint4 o;
        o.x = packh(a.x, a.y);
        o.y = packh(a.z, a.w);
        o.z = packh(b.x, b.y);
        o.w = packh(b.z, b.w);
        uint32_t off = SWZ((uint32_t)((row & 127) * 128 + colu * 16));
        *(uint4*)((char*)g_Qf + (size_t)(row >> 7) * 16384 + off) = o;
    }
}

// ---------------------------------------------------------------------------
// Kernel 2: fp16 flash attention with exponent shift (R15 verbatim).
// TQ=64, 128 thr/CTA, 2 CTAs/SM.  smem: Q 8K @0, K 2x16K @8192.
// ---------------------------------------------------------------------------
#define S_K0     8192
#define KBUF_STR 16384
#define SMEM_ATT 40960
#define ONES2    0x3C003C00u      // fp16 {1.0, 1.0}
#define PSHIFT   14.0f

__global__ __launch_bounds__(128, 2) void attn_kernel(float* __restrict__ out) {
    extern __shared__ __align__(1024) char smem[];
    const uint32_t sb = smem_u32(smem);

    const int tid  = threadIdx.x;
    const int wid  = tid >> 5;          // 0..3
    const int lane = tid & 31;
    const int quad = lane >> 2;
    const int tq   = lane & 3;
    const int m0   = wid * 16;          // within the 64-row Q tile
    const int b    = blockIdx.y;
    const int qt   = blockIdx.x;        // 64-row q tile within batch (0..63)
    const int q0   = qt * TQ;

    const char* gf = (const char*)g_Qf;
    const size_t tb0 = (size_t)(b * NTILES) * 16384;

    const float SC = 0.125f * 1.4426950408889634f;     // 1/sqrt(64) * log2(e)

    const uint32_t xorv  = (uint32_t)(lane & 7) << 4;
    const uint32_t qrowb = (uint32_t)(m0 + (lane & 7) + ((lane >> 3) & 1) * 8) * 128;
    const uint32_t srowb = (uint32_t)(((lane >> 4) * 8) + (lane & 7)) * 128;
    const uint32_t vrowb = (uint32_t)((lane >> 4) * 16 + (lane & 7) + ((lane >> 3) & 1) * 8) * 128;
    uint32_t qc[4], bc[4];
    #pragma unroll
    for (int c = 0; c < 4; ++c) {
        qc[c] = ((uint32_t)((lane >> 4) * 16 + c * 32)) ^ xorv;
        bc[c] = ((uint32_t)(((lane >> 3) & 1) * 16 + c * 32)) ^ xorv;
    }
    const uint32_t onesb[2] = {ONES2, ONES2};

    // ---- prologue: async copy Q half-block + first two K tiles ----
    {
        const size_t qoff = tb0 + (size_t)(qt >> 1) * 16384 + (size_t)(qt & 1) * 8192;
        #pragma unroll
        for (int i = 0; i < 4; ++i) {
            uint32_t o = (uint32_t)(tid + i * 128) * 16;    // 8KB
            CP16(sb + o, gf + qoff + o);
        }
        #pragma unroll
        for (int i = 0; i < 8; ++i) {                       // K tile 0 (16KB)
            uint32_t o = (uint32_t)(tid + i * 128) * 16;
            CP16(sb + S_K0 + o, gf + tb0 + o);
        }
        CP_COMMIT();
        #pragma unroll
        for (int i = 0; i < 8; ++i) {                       // K tile 1
            uint32_t o = (uint32_t)(tid + i * 128) * 16;
            CP16(sb + S_K0 + KBUF_STR + o, gf + tb0 + 16384 + o);
        }
        CP_COMMIT();
    }

    CP_WAIT(1);
    __syncthreads();

    // ---- Q fragments (persist) ----
    uint32_t qf[4][4];
    #pragma unroll
    for (int c = 0; c < 4; ++c)
        ldsm_x4(qf[c], sb + qrowb + qc[c]);

    float accO[8][4] = {};
    float accL[4]    = {};

    for (int kt = 0; kt < NTILES; ++kt) {
        CP_WAIT(1);
        __syncthreads();

        const uint32_t kb = sb + S_K0 + (uint32_t)(kt & 1) * KBUF_STR;

        // ---- S = Q K^T : 64 MMAs, 8 accumulators interleaved ----
        float accS[16][4] = {};
        #pragma unroll
        for (int c = 0; c < 4; ++c) {
            #pragma unroll
            for (int g4 = 0; g4 < 2; ++g4) {
                uint32_t bh[4][4];
                #pragma unroll
                for (int j = 0; j < 4; ++j)
                    ldsm_x4(bh[j], kb + srowb + bc[c] + (uint32_t)((g4 * 4 + j) * 2048));
                #pragma unroll
                for (int j = 0; j < 4; ++j) {
                    const int a = (g4 * 4 + j) * 2;
                    mma16816h(accS[a],     qf[c], bh[j]);
                    mma16816h(accS[a + 1], qf[c], bh[j] + 2);
                }
            }
        }

        // ---- softmax (no max): p' = exp2(s*SC - 14), pack fp16 ----
        uint32_t ph[8][4];
        #pragma unroll
        for (int njl = 0; njl < 16; ++njl) {
            float* s = accS[njl];
            float p0 = ex2f(s[0] * SC - PSHIFT);
            float p1 = ex2f(s[1] * SC - PSHIFT);
            float p2 = ex2f(s[2] * SC - PSHIFT);
            float p3 = ex2f(s[3] * SC - PSHIFT);
            const int c  = njl >> 1;
            const int sl = (njl & 1) * 2;
            ph[c][sl]     = packh(p0, p1);
            ph[c][sl + 1] = packh(p2, p3);
        }

        // ---- O += P V (64 MMAs) with row-sum MMAs interleaved (8) ----
        #pragma unroll
        for (int c2 = 0; c2 < 4; ++c2) {
            const uint32_t vko = (uint32_t)(c2 * 4096);
            mma16816h(accL, ph[c2 * 2],     onesb);
            #pragma unroll
            for (int njg = 0; njg < 2; ++njg) {
                uint32_t vh[4][4];
                #pragma unroll
                for (int j = 0; j < 4; ++j) {
                    const uint32_t colb = ((uint32_t)((njg * 4 + j) * 16)) ^ xorv;
                    ldsm_x4t(vh[j], kb + vrowb + colb + vko);
                }
                #pragma unroll
                for (int j = 0; j < 4; ++j)
                    mma16816h(accO[njg * 4 + j], ph[c2 * 2],     vh[j]);
                #pragma unroll
                for (int j = 0; j < 4; ++j)
                    mma16816h(accO[njg * 4 + j], ph[c2 * 2 + 1], vh[j] + 2);
            }
            mma16816h(accL, ph[c2 * 2 + 1], onesb);
        }

        __syncthreads();   // all warps done reading buf[kt&1]

        if (kt + 2 < NTILES) {
            const char* src = gf + tb0 + (size_t)(kt + 2) * 16384;
            const uint32_t dst = sb + S_K0 + (uint32_t)(kt & 1) * KBUF_STR;
            #pragma unroll
            for (int i = 0; i < 8; ++i) {
                uint32_t o = (uint32_t)(tid + i * 128) * 16;
                CP16(dst + o, src + o);
            }
        }
        CP_COMMIT();
    }

    // ---- epilogue ----
    const float inv0 = 1.0f / accL[0];
    const float inv8 = 1.0f / accL[2];

    const int r0 = q0 + m0 + quad;
    float* o0 = out + ((size_t)b * SEQ + r0) * HD;
    float* o8 = o0 + 8 * HD;
    #pragma unroll
    for (int nj = 0; nj < 8; ++nj) {
        const int col = nj * 8 + tq * 2;
        *(float2*)(o0 + col) = make_float2(accO[nj][0] * inv0, accO[nj][1] * inv0);
        *(float2*)(o8 + col) = make_float2(accO[nj][2] * inv8, accO[nj][3] * inv8);
    }
}

// ---------------------------------------------------------------------------
extern "C" void kernel_launch(void* const* d_in, const int* in_sizes, int n_in,
                              void* d_out, int out_size) {
    (void)in_sizes; (void)n_in; (void)out_size;
    const float* x  = (const float*)d_in[0];   // [4, 4096, 1024]
    const float* wq = (const float*)d_in[1];   // [64, 1024]
    float* out      = (float*)d_out;           // [4, 4096, 64]

    dim3 pgrid(NQ / 128, 4);
    qproj_kernel<<<pgrid, 128>>>(x, wq);
    qfin_kernel<<<128, 256>>>();

    cudaFuncSetAttribute(attn_kernel,
                         cudaFuncAttributeMaxDynamicSharedMemorySize, SMEM_ATT);
    dim3 grid(SEQ / TQ, BSZ);
    attn_kernel<<<grid, 128, SMEM_ATT>>>(out);
}

// round 17
// speedup vs baseline: 1.0749x; 1.0749x over previous
#include <cuda_runtime.h>
#include <cuda_bf16.h>
#include <math_constants.h>
#include <cstdint>
#include <cstddef>

#define BSZ    4
#define SEQ    4096
#define DMODEL 1024
#define HD     64
#define NQ     (BSZ * SEQ)

#define TQ     64           // queries per CTA (2 CTAs/SM) in attention
#define TK     128
#define NTILES (SEQ / TK)   // 32

// Projected q (= k = v) as fp16, PRE-SWIZZLED in 16KB blocks of 128 rows.
__device__ __align__(16) uint32_t g_Qf[(size_t)NQ * HD / 2];

// ---------------------------------------------------------------------------
// helpers
// ---------------------------------------------------------------------------
__device__ __forceinline__ uint32_t smem_u32(const void* p) {
    uint32_t a;
    asm("{ .reg .u64 t; cvta.to.shared.u64 t, %1; cvt.u32.u64 %0, t; }"
        : "=r"(a) : "l"(p));
    return a;
}
__device__ __forceinline__ float ex2f(float x) {
    float y; asm("ex2.approx.ftz.f32 %0, %1;" : "=f"(y) : "f"(x)); return y;
}
__device__ __forceinline__ uint32_t packbf(float lo, float hi) {
    uint32_t r;
    asm("cvt.rn.bf16x2.f32 %0, %1, %2;" : "=r"(r) : "f"(hi), "f"(lo));
    return r;
}
__device__ __forceinline__ uint32_t packh(float lo, float hi) {
    uint32_t r;
    asm("cvt.rn.f16x2.f32 %0, %1, %2;" : "=r"(r) : "f"(hi), "f"(lo));
    return r;
}

#define SWZ(o) ((o) ^ (((o) >> 3) & 0x70))

__device__ __forceinline__ void ldsm_x4(uint32_t r[4], uint32_t addr) {
    asm volatile("ldmatrix.sync.aligned.m8n8.x4.shared.b16 {%0,%1,%2,%3}, [%4];"
                 : "=r"(r[0]), "=r"(r[1]), "=r"(r[2]), "=r"(r[3]) : "r"(addr));
}
__device__ __forceinline__ void ldsm_x4t(uint32_t r[4], uint32_t addr) {
    asm volatile("ldmatrix.sync.aligned.m8n8.x4.trans.shared.b16 {%0,%1,%2,%3}, [%4];"
                 : "=r"(r[0]), "=r"(r[1]), "=r"(r[2]), "=r"(r[3]) : "r"(addr));
}
// bf16 mma (projection)
__device__ __forceinline__ void mma16816(float d[4], const uint32_t a[4],
                                         const uint32_t b[2]) {
    asm volatile(
        "mma.sync.aligned.m16n8k16.row.col.f32.bf16.bf16.f32 "
        "{%0,%1,%2,%3}, {%4,%5,%6,%7}, {%8,%9}, {%0,%1,%2,%3};"
        : "+f"(d[0]), "+f"(d[1]), "+f"(d[2]), "+f"(d[3])
        : "r"(a[0]), "r"(a[1]), "r"(a[2]), "r"(a[3]), "r"(b[0]), "r"(b[1]));
}
// fp16 mma (attention)
__device__ __forceinline__ void mma16816h(float d[4], const uint32_t a[4],
                                          const uint32_t b[2]) {
    asm volatile(
        "mma.sync.aligned.m16n8k16.row.col.f32.f16.f16.f32 "
        "{%0,%1,%2,%3}, {%4,%5,%6,%7}, {%8,%9}, {%0,%1,%2,%3};"
        : "+f"(d[0]), "+f"(d[1]), "+f"(d[2]), "+f"(d[3])
        : "r"(a[0]), "r"(a[1]), "r"(a[2]), "r"(a[3]), "r"(b[0]), "r"(b[1]));
}

#define CP16(dst, src) \
    asm volatile("cp.async.cg.shared.global [%0], [%1], 16;" :: "r"(dst), "l"(src))
#define CP_COMMIT() asm volatile("cp.async.commit_group;" ::: "memory")
#define CP_WAIT(n)  asm volatile("cp.async.wait_group %0;" :: "n"(n) : "memory")

__device__ __forceinline__ void split_store4(char* base_h, char* base_l, uint32_t off,
                                             float v0, float v1, float v2, float v3) {
    uint32_t h0 = packbf(v0, v1);
    uint32_t h1 = packbf(v2, v3);
    float f00 = __uint_as_float(h0 << 16);
    float f01 = __uint_as_float(h0 & 0xffff0000u);
    float f10 = __uint_as_float(h1 << 16);
    float f11 = __uint_as_float(h1 & 0xffff0000u);
    uint32_t l0 = packbf(v0 - f00, v1 - f01);
    uint32_t l1 = packbf(v2 - f10, v3 - f11);
    *(uint2*)(base_h + off) = make_uint2(h0, h1);
    *(uint2*)(base_l + off) = make_uint2(l0, l1);
}

// ---------------------------------------------------------------------------
// Kernel 1: Q projection, bf16x3 tensor GEMM, 64-row CTAs, 3 CTAs/SM.
// No split-K, no partial traffic.  smem 32KB: X hi/lo 8K+8K, W hi/lo 8K+8K.
// ---------------------------------------------------------------------------
#define PX_H 0
#define PX_L 8192
#define PW_H 16384
#define PW_L 24576

__global__ __launch_bounds__(128, 3) void qproj_kernel(const float* __restrict__ X,
                                                       const float* __restrict__ W) {
    __shared__ __align__(1024) char psm[32768];
    const uint32_t sb = smem_u32(psm);

    const int tid  = threadIdx.x;
    const int wid  = tid >> 5;          // 0..3
    const int lane = tid & 31;
    const int quad = lane >> 2;
    const int tq   = lane & 3;
    const int m0   = wid * 16;          // warp's 16 rows within 64-row block
    const int row0 = blockIdx.x * 64;

    const uint32_t xorv  = (uint32_t)(lane & 7) << 4;
    const uint32_t qrowb = (uint32_t)(m0 + (lane & 7) + ((lane >> 3) & 1) * 8) * 128;
    const uint32_t browb = (uint32_t)(((lane >> 4) * 8) + (lane & 7)) * 128;
    uint32_t qc[4], bc[4];
    #pragma unroll
    for (int c = 0; c < 4; ++c) {
        qc[c] = ((uint32_t)((lane >> 4) * 16 + c * 32)) ^ xorv;
        bc[c] = ((uint32_t)(((lane >> 3) & 1) * 16 + c * 32)) ^ xorv;
    }

    float accQ[8][4] = {};

    #pragma unroll 1
    for (int kc = 0; kc < 16; ++kc) {
        // X chunk [64][64] -> split bf16 (8 float4/thread)
        #pragma unroll
        for (int it = 0; it < 8; ++it) {
            int idx = tid + it * 128;          // 0..1023
            int r = idx >> 4, c4 = idx & 15;
            float4 v = *(const float4*)(X + (size_t)(row0 + r) * DMODEL + kc * 64 + c4 * 4);
            split_store4(psm + PX_H, psm + PX_L, SWZ((uint32_t)(r * 128 + c4 * 8)),
                         v.x, v.y, v.z, v.w);
        }
        // W chunk [64][64] (8 float4/thread)
        #pragma unroll
        for (int it = 0; it < 8; ++it) {
            int idx = tid + it * 128;
            int n = idx >> 4, c4 = idx & 15;
            float4 v = *(const float4*)(W + (size_t)n * DMODEL + kc * 64 + c4 * 4);
            split_store4(psm + PW_H, psm + PW_L, SWZ((uint32_t)(n * 128 + c4 * 8)),
                         v.x, v.y, v.z, v.w);
        }
        __syncthreads();

        uint32_t ah[4][4], al[4][4];
        #pragma unroll
        for (int c = 0; c < 4; ++c) {
            ldsm_x4(ah[c], sb + PX_H + qrowb + qc[c]);
            ldsm_x4(al[c], sb + PX_L + qrowb + qc[c]);
        }
        #pragma unroll
        for (int njp = 0; njp < 4; ++njp) {
            #pragma unroll
            for (int c = 0; c < 4; ++c) {
                uint32_t bh[4], bl[4];
                ldsm_x4(bh, sb + PW_H + browb + bc[c] + (uint32_t)(njp * 2048));
                ldsm_x4(bl, sb + PW_L + browb + bc[c] + (uint32_t)(njp * 2048));
                mma16816(accQ[njp * 2],     ah[c], bh);
                mma16816(accQ[njp * 2 + 1], ah[c], bh + 2);
                mma16816(accQ[njp * 2],     ah[c], bl);
                mma16816(accQ[njp * 2 + 1], ah[c], bl + 2);
                mma16816(accQ[njp * 2],     al[c], bh);
                mma16816(accQ[njp * 2 + 1], al[c], bh + 2);
            }
        }
        __syncthreads();
    }

    // fp16 epilogue (swizzled); this CTA is the (row0&64) half of a 128-row block
    char* gqf = (char*)g_Qf + (size_t)(row0 >> 7) * 16384;
    const uint32_t rhi = (uint32_t)(row0 & 64);
    #pragma unroll
    for (int nj = 0; nj < 8; ++nj) {
        uint32_t colb = (uint32_t)((nj * 8 + tq * 2) * 2);
        uint32_t offA = SWZ((rhi + (uint32_t)(m0 + quad)) * 128 + colb);
        uint32_t offB = SWZ((rhi + (uint32_t)(m0 + quad + 8)) * 128 + colb);
        *(uint32_t*)(gqf + offA) = packh(accQ[nj][0], accQ[nj][1]);
        *(uint32_t*)(gqf + offB) = packh(accQ[nj][2], accQ[nj][3]);
    }
}

// ---------------------------------------------------------------------------
// Kernel 2: fp16 flash attention with exponent shift (R15 verbatim, 52.1us).
// TQ=64, 128 thr/CTA, 2 CTAs/SM.  smem: Q 8K @0, K 2x16K @8192.
// ---------------------------------------------------------------------------
#define S_K0     8192
#define KBUF_STR 16384
#define SMEM_ATT 40960
#define ONES2    0x3C003C00u      // fp16 {1.0, 1.0}
#define PSHIFT   14.0f

__global__ __launch_bounds__(128, 2) void attn_kernel(float* __restrict__ out) {
    extern __shared__ __align__(1024) char smem[];
    const uint32_t sb = smem_u32(smem);

    const int tid  = threadIdx.x;
    const int wid  = tid >> 5;          // 0..3
    const int lane = tid & 31;
    const int quad = lane >> 2;
    const int tq   = lane & 3;
    const int m0   = wid * 16;          // within the 64-row Q tile
    const int b    = blockIdx.y;
    const int qt   = blockIdx.x;        // 64-row q tile within batch (0..63)
    const int q0   = qt * TQ;

    const char* gf = (const char*)g_Qf;
    const size_t tb0 = (size_t)(b * NTILES) * 16384;

    const float SC = 0.125f * 1.4426950408889634f;     // 1/sqrt(64) * log2(e)

    const uint32_t xorv  = (uint32_t)(lane & 7) << 4;
    const uint32_t qrowb = (uint32_t)(m0 + (lane & 7) + ((lane >> 3) & 1) * 8) * 128;
    const uint32_t srowb = (uint32_t)(((lane >> 4) * 8) + (lane & 7)) * 128;
    const uint32_t vrowb = (uint32_t)((lane >> 4) * 16 + (lane & 7) + ((lane >> 3) & 1) * 8) * 128;
    uint32_t qc[4], bc[4];
    #pragma unroll
    for (int c = 0; c < 4; ++c) {
        qc[c] = ((uint32_t)((lane >> 4) * 16 + c * 32)) ^ xorv;
        bc[c] = ((uint32_t)(((lane >> 3) & 1) * 16 + c * 32)) ^ xorv;
    }
    const uint32_t onesb[2] = {ONES2, ONES2};

    // ---- prologue: async copy Q half-block + first two K tiles ----
    {
        const size_t qoff = tb0 + (size_t)(qt >> 1) * 16384 + (size_t)(qt & 1) * 8192;
        #pragma unroll
        for (int i = 0; i < 4; ++i) {
            uint32_t o = (uint32_t)(tid + i * 128) * 16;    // 8KB
            CP16(sb + o, gf + qoff + o);
        }
        #pragma unroll
        for (int i = 0; i < 8; ++i) {                       // K tile 0 (16KB)
            uint32_t o = (uint32_t)(tid + i * 128) * 16;
            CP16(sb + S_K0 + o, gf + tb0 + o);
        }
        CP_COMMIT();
        #pragma unroll
        for (int i = 0; i < 8; ++i) {                       // K tile 1
            uint32_t o = (uint32_t)(tid + i * 128) * 16;
            CP16(sb + S_K0 + KBUF_STR + o, gf + tb0 + 16384 + o);
        }
        CP_COMMIT();
    }

    CP_WAIT(1);
    __syncthreads();

    // ---- Q fragments (persist) ----
    uint32_t qf[4][4];
    #pragma unroll
    for (int c = 0; c < 4; ++c)
        ldsm_x4(qf[c], sb + qrowb + qc[c]);

    float accO[8][4] = {};
    float accL[4]    = {};

    for (int kt = 0; kt < NTILES; ++kt) {
        CP_WAIT(1);
        __syncthreads();

        const uint32_t kb = sb + S_K0 + (uint32_t)(kt & 1) * KBUF_STR;

        // ---- S = Q K^T : 64 MMAs, 8 accumulators interleaved ----
        float accS[16][4] = {};
        #pragma unroll
        for (int c = 0; c < 4; ++c) {
            #pragma unroll
            for (int g4 = 0; g4 < 2; ++g4) {
                uint32_t bh[4][4];
                #pragma unroll
                for (int j = 0; j < 4; ++j)
                    ldsm_x4(bh[j], kb + srowb + bc[c] + (uint32_t)((g4 * 4 + j) * 2048));
                #pragma unroll
                for (int j = 0; j < 4; ++j) {
                    const int a = (g4 * 4 + j) * 2;
                    mma16816h(accS[a],     qf[c], bh[j]);
                    mma16816h(accS[a + 1], qf[c], bh[j] + 2);
                }
            }
        }

        // ---- softmax (no max): p' = exp2(s*SC - 14), pack fp16 ----
        uint32_t ph[8][4];
        #pragma unroll
        for (int njl = 0; njl < 16; ++njl) {
            float* s = accS[njl];
            float p0 = ex2f(s[0] * SC - PSHIFT);
            float p1 = ex2f(s[1] * SC - PSHIFT);
            float p2 = ex2f(s[2] * SC - PSHIFT);
            float p3 = ex2f(s[3] * SC - PSHIFT);
            const int c  = njl >> 1;
            const int sl = (njl & 1) * 2;
            ph[c][sl]     = packh(p0, p1);
            ph[c][sl + 1] = packh(p2, p3);
        }

        // ---- O += P V (64 MMAs) with row-sum MMAs interleaved (8) ----
        #pragma unroll
        for (int c2 = 0; c2 < 4; ++c2) {
            const uint32_t vko = (uint32_t)(c2 * 4096);
            mma16816h(accL, ph[c2 * 2],     onesb);
            #pragma unroll
            for (int njg = 0; njg < 2; ++njg) {
                uint32_t vh[4][4];
                #pragma unroll
                for (int j = 0; j < 4; ++j) {
                    const uint32_t colb = ((uint32_t)((njg * 4 + j) * 16)) ^ xorv;
                    ldsm_x4t(vh[j], kb + vrowb + colb + vko);
                }
                #pragma unroll
                for (int j = 0; j < 4; ++j)
                    mma16816h(accO[njg * 4 + j], ph[c2 * 2],     vh[j]);
                #pragma unroll
                for (int j = 0; j < 4; ++j)
                    mma16816h(accO[njg * 4 + j], ph[c2 * 2 + 1], vh[j] + 2);
            }
            mma16816h(accL, ph[c2 * 2 + 1], onesb);
        }

        __syncthreads();   // all warps done reading buf[kt&1]

        if (kt + 2 < NTILES) {
            const char* src = gf + tb0 + (size_t)(kt + 2) * 16384;
            const uint32_t dst = sb + S_K0 + (uint32_t)(kt & 1) * KBUF_STR;
            #pragma unroll
            for (int i = 0; i < 8; ++i) {
                uint32_t o = (uint32_t)(tid + i * 128) * 16;
                CP16(dst + o, src + o);
            }
        }
        CP_COMMIT();
    }

    // ---- epilogue ----
    const float inv0 = 1.0f / accL[0];
    const float inv8 = 1.0f / accL[2];

    const int r0 = q0 + m0 + quad;
    float* o0 = out + ((size_t)b * SEQ + r0) * HD;
    float* o8 = o0 + 8 * HD;
    #pragma unroll
    for (int nj = 0; nj < 8; ++nj) {
        const int col = nj * 8 + tq * 2;
        *(float2*)(o0 + col) = make_float2(accO[nj][0] * inv0, accO[nj][1] * inv0);
        *(float2*)(o8 + col) = make_float2(accO[nj][2] * inv8, accO[nj][3] * inv8);
    }
}

// ---------------------------------------------------------------------------
extern "C" void kernel_launch(void* const* d_in, const int* in_sizes, int n_in,
                              void* d_out, int out_size) {
    (void)in_sizes; (void)n_in; (void)out_size;
    const float* x  = (const float*)d_in[0];   // [4, 4096, 1024]
    const float* wq = (const float*)d_in[1];   // [64, 1024]
    float* out      = (float*)d_out;           // [4, 4096, 64]

    qproj_kernel<<<NQ / 64, 128>>>(x, wq);

    cudaFuncSetAttribute(attn_kernel,
                         cudaFuncAttributeMaxDynamicSharedMemorySize, SMEM_ATT);
    dim3 grid(SEQ / TQ, BSZ);
    attn_kernel<<<grid, 128, SMEM_ATT>>>(out);
}